// round 1
// baseline (speedup 1.0000x reference)
#include <cuda_runtime.h>
#include <cstdint>

#define N_TOK   65536
#define K_IN    64
#define E_DIM   512
#define V_SIZE  2048

// ---- scratch (device globals: no runtime allocation allowed) ----
__device__ float g_zp[(size_t)N_TOK * E_DIM];   // pre-conv output  [N, 512]
__device__ float g_C [N_TOK];                   // |zp|^2 per row
__device__ float g_e2[V_SIZE];                  // |emb|^2 per code
__device__ int   g_tok[N_TOK];                  // argmin tokens

// ============================================================
// Kernel 0: e2[v] = sum_k emb[v,k]^2
// ============================================================
__global__ void e2_kernel(const float* __restrict__ emb) {
    int v = blockIdx.x;
    const float* row = emb + (size_t)v * E_DIM;
    float s = 0.f;
    for (int k = threadIdx.x; k < E_DIM; k += 128) {
        float x = row[k];
        s = fmaf(x, x, s);
    }
    // warp reduce
    for (int off = 16; off > 0; off >>= 1)
        s += __shfl_down_sync(0xffffffffu, s, off);
    __shared__ float ws[4];
    int lane = threadIdx.x & 31, warp = threadIdx.x >> 5;
    if (lane == 0) ws[warp] = s;
    __syncthreads();
    if (threadIdx.x == 0)
        g_e2[v] = ws[0] + ws[1] + ws[2] + ws[3];
}

// ============================================================
// Kernel 1: zp = z @ pre_W + pre_b, and C = |zp|^2
// one block per row, 128 threads, each thread -> 4 output cols
// ============================================================
__global__ __launch_bounds__(128) void pre_kernel(
    const float* __restrict__ z, const float* __restrict__ W,
    const float* __restrict__ b)
{
    int n = blockIdx.x;
    __shared__ float zs[K_IN];
    if (threadIdx.x < K_IN) zs[threadIdx.x] = z[(size_t)n * K_IN + threadIdx.x];
    __syncthreads();

    int j0 = threadIdx.x;
    float acc[4];
    #pragma unroll
    for (int i = 0; i < 4; i++) acc[i] = b[j0 + 128 * i];

    #pragma unroll 8
    for (int k = 0; k < K_IN; k++) {
        float zk = zs[k];
        const float* Wr = W + (size_t)k * E_DIM + j0;
        #pragma unroll
        for (int i = 0; i < 4; i++)
            acc[i] = fmaf(zk, Wr[128 * i], acc[i]);
    }

    float* zpr = g_zp + (size_t)n * E_DIM + j0;
    float s = 0.f;
    #pragma unroll
    for (int i = 0; i < 4; i++) {
        zpr[128 * i] = acc[i];
        s = fmaf(acc[i], acc[i], s);
    }
    for (int off = 16; off > 0; off >>= 1)
        s += __shfl_down_sync(0xffffffffu, s, off);
    __shared__ float ws[4];
    int lane = threadIdx.x & 31, warp = threadIdx.x >> 5;
    if (lane == 0) ws[warp] = s;
    __syncthreads();
    if (threadIdx.x == 0)
        g_C[n] = ws[0] + ws[1] + ws[2] + ws[3];
}

// ============================================================
// Kernel 2: fused distance GEMM + argmin
// d[n,v] = C[n] + e2[v] - 2 * dot(zp[n], emb[v]);  tok[n]=argmin_v d
// block tile: 64 rows x 64 codes x K32, 256 threads (16x16), 4x4/thread
// ============================================================
#define BM 64
#define BV 64
#define BK 32

__global__ __launch_bounds__(256) void dist_kernel(
    const float* __restrict__ emb, float* __restrict__ out_tok)
{
    __shared__ float As[BK][BM + 4];
    __shared__ float Bs[BK][BV + 4];
    __shared__ float redv[BM * 16];
    __shared__ int   redi[BM * 16];

    int m0  = blockIdx.x * BM;
    int tid = threadIdx.x;
    int tx  = tid & 15;   // code direction
    int ty  = tid >> 4;   // row direction

    float bestv[4];
    int   besti[4];
    #pragma unroll
    for (int i = 0; i < 4; i++) { bestv[i] = 3.4e38f; besti[i] = 0; }

    float Ci[4];
    #pragma unroll
    for (int i = 0; i < 4; i++) Ci[i] = g_C[m0 + ty * 4 + i];

    for (int v0 = 0; v0 < V_SIZE; v0 += BV) {
        float acc[4][4];
        #pragma unroll
        for (int i = 0; i < 4; i++)
            #pragma unroll
            for (int j = 0; j < 4; j++) acc[i][j] = 0.f;

        for (int k0 = 0; k0 < E_DIM; k0 += BK) {
            #pragma unroll
            for (int i = 0; i < 8; i++) {
                int idx = tid + 256 * i;
                int m = idx >> 5, kk = idx & 31;
                As[kk][m] = g_zp[(size_t)(m0 + m) * E_DIM + k0 + kk];
                Bs[kk][m] = emb [(size_t)(v0 + m) * E_DIM + k0 + kk];
            }
            __syncthreads();
            #pragma unroll
            for (int kk = 0; kk < BK; kk++) {
                float a[4], bb[4];
                *(float4*)a  = *(const float4*)&As[kk][ty * 4];
                *(float4*)bb = *(const float4*)&Bs[kk][tx * 4];
                #pragma unroll
                for (int i = 0; i < 4; i++)
                    #pragma unroll
                    for (int j = 0; j < 4; j++)
                        acc[i][j] = fmaf(a[i], bb[j], acc[i][j]);
            }
            __syncthreads();
        }
        // fold this code tile into running argmin
        #pragma unroll
        for (int j = 0; j < 4; j++) {
            int v = v0 + tx * 4 + j;
            float e2v = g_e2[v];
            #pragma unroll
            for (int i = 0; i < 4; i++) {
                // matches XLA's round((a+b) - 2c): 2c exact, single final rounding
                float d = fmaf(-2.0f, acc[i][j], Ci[i] + e2v);
                if (d < bestv[i]) { bestv[i] = d; besti[i] = v; }
            }
        }
    }

    // cross-thread reduce: 16 threads (tx) per row
    #pragma unroll
    for (int i = 0; i < 4; i++) {
        redv[(ty * 4 + i) * 16 + tx] = bestv[i];
        redi[(ty * 4 + i) * 16 + tx] = besti[i];
    }
    __syncthreads();
    if (tid < BM) {
        float bv = redv[tid * 16];
        int   bi = redi[tid * 16];
        #pragma unroll
        for (int t = 1; t < 16; t++) {
            float v = redv[tid * 16 + t];
            int   ii = redi[tid * 16 + t];
            if (v < bv || (v == bv && ii < bi)) { bv = v; bi = ii; }
        }
        g_tok[m0 + tid] = bi;
        out_tok[m0 + tid] = (float)bi;   // tokens as float in output slot 0
    }
}

// ============================================================
// Kernel 3: z_q = emb[tok] @ post_W + post_b  -> out (after tokens)
// same tiling: 64 rows x 64 cols (full) x K32
// ============================================================
__global__ __launch_bounds__(256) void post_kernel(
    const float* __restrict__ emb, const float* __restrict__ W,
    const float* __restrict__ b, float* __restrict__ out)
{
    __shared__ float As[BK][BM + 4];
    __shared__ float Bs[BK][64 + 4];
    __shared__ int   toks[BM];

    int m0  = blockIdx.x * BM;
    int tid = threadIdx.x;
    int tx  = tid & 15;
    int ty  = tid >> 4;

    if (tid < BM) toks[tid] = g_tok[m0 + tid];
    __syncthreads();

    float acc[4][4];
    #pragma unroll
    for (int i = 0; i < 4; i++)
        #pragma unroll
        for (int j = 0; j < 4; j++) acc[i][j] = 0.f;

    for (int k0 = 0; k0 < E_DIM; k0 += BK) {
        #pragma unroll
        for (int i = 0; i < 8; i++) {
            int idx = tid + 256 * i;
            int m = idx >> 5, kk = idx & 31;
            As[kk][m] = emb[(size_t)toks[m] * E_DIM + k0 + kk];
        }
        #pragma unroll
        for (int i = 0; i < 8; i++) {
            int idx = tid + 256 * i;
            int kk = idx >> 6, j = idx & 63;
            Bs[kk][j] = W[(size_t)(k0 + kk) * 64 + j];
        }
        __syncthreads();
        #pragma unroll
        for (int kk = 0; kk < BK; kk++) {
            float a[4], bb[4];
            *(float4*)a  = *(const float4*)&As[kk][ty * 4];
            *(float4*)bb = *(const float4*)&Bs[kk][tx * 4];
            #pragma unroll
            for (int i = 0; i < 4; i++)
                #pragma unroll
                for (int j = 0; j < 4; j++)
                    acc[i][j] = fmaf(a[i], bb[j], acc[i][j]);
        }
        __syncthreads();
    }

    float bb0 = b[tx * 4 + 0], bb1 = b[tx * 4 + 1],
          bb2 = b[tx * 4 + 2], bb3 = b[tx * 4 + 3];
    #pragma unroll
    for (int i = 0; i < 4; i++) {
        int n = m0 + ty * 4 + i;
        float4 r;
        r.x = acc[i][0] + bb0;
        r.y = acc[i][1] + bb1;
        r.z = acc[i][2] + bb2;
        r.w = acc[i][3] + bb3;
        *(float4*)&out[(size_t)n * 64 + tx * 4] = r;
    }
}

// ============================================================
extern "C" void kernel_launch(void* const* d_in, const int* in_sizes, int n_in,
                              void* d_out, int out_size)
{
    const float* z      = (const float*)d_in[0];   // [N, 64]
    const float* emb_W  = (const float*)d_in[1];   // [2048, 512]
    const float* pre_W  = (const float*)d_in[2];   // [64, 512]
    const float* pre_b  = (const float*)d_in[3];   // [512]
    const float* post_W = (const float*)d_in[4];   // [512, 64]
    const float* post_b = (const float*)d_in[5];   // [64]

    float* out = (float*)d_out;
    float* out_tok = out;                 // [N] tokens (as float)
    float* out_zq  = out + N_TOK;         // [N, 64]

    e2_kernel  <<<V_SIZE, 128>>>(emb_W);
    pre_kernel <<<N_TOK, 128>>>(z, pre_W, pre_b);
    dist_kernel<<<N_TOK / BM, 256>>>(emb_W, out_tok);
    post_kernel<<<N_TOK / BM, 256>>>(emb_W, post_W, post_b, out_zq);
}

// round 2
// speedup vs baseline: 1.9212x; 1.9212x over previous
#include <cuda_runtime.h>
#include <cstdint>

#define N_TOK   65536
#define K_IN    64
#define E_DIM   512
#define V_SIZE  2048

typedef unsigned long long ull;

// ---- scratch (device globals: no runtime allocation allowed) ----
__device__ float g_zp[(size_t)N_TOK * E_DIM];   // pre-conv output  [N, 512]
__device__ float g_C [N_TOK];                   // |zp|^2 per row
__device__ float g_e2[V_SIZE];                  // |emb|^2 per code
__device__ int   g_tok[N_TOK];                  // argmin tokens

// ---- packed fp32x2 helpers (Blackwell FFMA2; each lane is exact IEEE fp32 FMA) ----
__device__ __forceinline__ ull fma2(ull a, ull b, ull c) {
    ull d;
    asm("fma.rn.f32x2 %0, %1, %2, %3;" : "=l"(d) : "l"(a), "l"(b), "l"(c));
    return d;
}
__device__ __forceinline__ ull dup2(float x) {
    ull d;
    asm("mov.b64 %0, {%1, %1};" : "=l"(d) : "f"(x));
    return d;
}
__device__ __forceinline__ ull pack2(float x, float y) {
    ull d;
    asm("mov.b64 %0, {%1, %2};" : "=l"(d) : "f"(x), "f"(y));
    return d;
}
__device__ __forceinline__ float2 unpack2(ull v) {
    float2 r;
    asm("mov.b64 {%0, %1}, %2;" : "=f"(r.x), "=f"(r.y) : "l"(v));
    return r;
}

// ============================================================
// Kernel 0: e2[v] = sum_k emb[v,k]^2
// ============================================================
__global__ void e2_kernel(const float* __restrict__ emb) {
    int v = blockIdx.x;
    const float* row = emb + (size_t)v * E_DIM;
    float s = 0.f;
    for (int k = threadIdx.x; k < E_DIM; k += 128) {
        float x = row[k];
        s = fmaf(x, x, s);
    }
    for (int off = 16; off > 0; off >>= 1)
        s += __shfl_down_sync(0xffffffffu, s, off);
    __shared__ float ws[4];
    int lane = threadIdx.x & 31, warp = threadIdx.x >> 5;
    if (lane == 0) ws[warp] = s;
    __syncthreads();
    if (threadIdx.x == 0)
        g_e2[v] = ws[0] + ws[1] + ws[2] + ws[3];
}

// ============================================================
// Kernel 1: zp = z @ pre_W + pre_b, and C = |zp|^2
// ============================================================
__global__ __launch_bounds__(128) void pre_kernel(
    const float* __restrict__ z, const float* __restrict__ W,
    const float* __restrict__ b)
{
    int n = blockIdx.x;
    __shared__ float zs[K_IN];
    if (threadIdx.x < K_IN) zs[threadIdx.x] = z[(size_t)n * K_IN + threadIdx.x];
    __syncthreads();

    int j0 = threadIdx.x;
    float acc[4];
    #pragma unroll
    for (int i = 0; i < 4; i++) acc[i] = b[j0 + 128 * i];

    #pragma unroll 8
    for (int k = 0; k < K_IN; k++) {
        float zk = zs[k];
        const float* Wr = W + (size_t)k * E_DIM + j0;
        #pragma unroll
        for (int i = 0; i < 4; i++)
            acc[i] = fmaf(zk, Wr[128 * i], acc[i]);
    }

    float* zpr = g_zp + (size_t)n * E_DIM + j0;
    float s = 0.f;
    #pragma unroll
    for (int i = 0; i < 4; i++) {
        zpr[128 * i] = acc[i];
        s = fmaf(acc[i], acc[i], s);
    }
    for (int off = 16; off > 0; off >>= 1)
        s += __shfl_down_sync(0xffffffffu, s, off);
    __shared__ float ws[4];
    int lane = threadIdx.x & 31, warp = threadIdx.x >> 5;
    if (lane == 0) ws[warp] = s;
    __syncthreads();
    if (threadIdx.x == 0)
        g_C[n] = ws[0] + ws[1] + ws[2] + ws[3];
}

// ============================================================
// Kernel 2: fused distance GEMM + argmin, packed FFMA2
// block tile 128 rows x 256 codes x K16; 256 threads (16x16);
// per thread 8 rows x 16 codes; accumulators in f32x2 pairs.
// Per-lane math is bitwise identical to the scalar version:
// sequential k=0..511 FMA chain per output, then
// d = fmaf(-2, dot, C + e2).
// ============================================================
#define DBM 128
#define DBV 256
#define DBK 16

__global__ __launch_bounds__(256, 1) void dist_kernel(
    const float* __restrict__ emb, float* __restrict__ out_tok)
{
    __shared__ float As[DBK][DBM + 4];
    __shared__ float Bs[DBK][DBV + 4];

    int m0  = blockIdx.x * DBM;
    int tid = threadIdx.x;
    int tx  = tid & 15;    // code direction (16 threads)
    int ty  = tid >> 4;    // row direction  (16 threads)
    int row0 = ty * 8;

    float Ci[8];
    #pragma unroll
    for (int i = 0; i < 8; i++) Ci[i] = g_C[m0 + row0 + i];

    float bestv[8];
    int   besti[8];
    #pragma unroll
    for (int i = 0; i < 8; i++) { bestv[i] = 3.4e38f; besti[i] = 0; }

    for (int v0 = 0; v0 < V_SIZE; v0 += DBV) {
        ull acc[8][8];   // [row i][g*2+p] ; lanes = codes (even,odd)
        #pragma unroll
        for (int i = 0; i < 8; i++)
            #pragma unroll
            for (int j = 0; j < 8; j++) acc[i][j] = 0ull;

        for (int k0 = 0; k0 < E_DIM; k0 += DBK) {
            // fill As: 128 x 16 = 512 float4 chunks, 2 per thread
            #pragma unroll
            for (int l = 0; l < 2; l++) {
                int chunk = tid + 256 * l;
                int m = chunk >> 2, kq = chunk & 3;
                float4 v = *(const float4*)(g_zp + (size_t)(m0 + m) * E_DIM + k0 + kq * 4);
                As[kq * 4 + 0][m] = v.x;
                As[kq * 4 + 1][m] = v.y;
                As[kq * 4 + 2][m] = v.z;
                As[kq * 4 + 3][m] = v.w;
            }
            // fill Bs: 256 x 16 = 1024 float4 chunks, 4 per thread
            #pragma unroll
            for (int l = 0; l < 4; l++) {
                int chunk = tid + 256 * l;
                int vm = chunk >> 2, kq = chunk & 3;
                float4 v = *(const float4*)(emb + (size_t)(v0 + vm) * E_DIM + k0 + kq * 4);
                Bs[kq * 4 + 0][vm] = v.x;
                Bs[kq * 4 + 1][vm] = v.y;
                Bs[kq * 4 + 2][vm] = v.z;
                Bs[kq * 4 + 3][vm] = v.w;
            }
            __syncthreads();

            #pragma unroll
            for (int kk = 0; kk < DBK; kk++) {
                // a: 8 rows, broadcast across tx (conflict-free)
                float4 a01 = *(const float4*)&As[kk][row0];
                float4 a23 = *(const float4*)&As[kk][row0 + 4];
                ull ad[8];
                ad[0] = dup2(a01.x); ad[1] = dup2(a01.y);
                ad[2] = dup2(a01.z); ad[3] = dup2(a01.w);
                ad[4] = dup2(a23.x); ad[5] = dup2(a23.y);
                ad[6] = dup2(a23.z); ad[7] = dup2(a23.w);
                // b: 4 groups; warp lanes read consecutive float4 -> conflict-free
                #pragma unroll
                for (int g = 0; g < 4; g++) {
                    float4 b = *(const float4*)&Bs[kk][(g * 16 + tx) * 4];
                    ull b0 = pack2(b.x, b.y);
                    ull b1 = pack2(b.z, b.w);
                    #pragma unroll
                    for (int i = 0; i < 8; i++) {
                        acc[i][g * 2 + 0] = fma2(ad[i], b0, acc[i][g * 2 + 0]);
                        acc[i][g * 2 + 1] = fma2(ad[i], b1, acc[i][g * 2 + 1]);
                    }
                }
            }
            __syncthreads();
        }

        // fold this 256-code tile into the running argmin
        #pragma unroll
        for (int g = 0; g < 4; g++) {
            int vb = v0 + (g * 16 + tx) * 4;
            float e0 = g_e2[vb + 0];
            float e1 = g_e2[vb + 1];
            float e2v = g_e2[vb + 2];
            float e3 = g_e2[vb + 3];
            #pragma unroll
            for (int i = 0; i < 8; i++) {
                float2 p0 = unpack2(acc[i][g * 2 + 0]);
                float2 p1 = unpack2(acc[i][g * 2 + 1]);
                float d;
                d = fmaf(-2.0f, p0.x, Ci[i] + e0);
                if (d < bestv[i]) { bestv[i] = d; besti[i] = vb + 0; }
                d = fmaf(-2.0f, p0.y, Ci[i] + e1);
                if (d < bestv[i]) { bestv[i] = d; besti[i] = vb + 1; }
                d = fmaf(-2.0f, p1.x, Ci[i] + e2v);
                if (d < bestv[i]) { bestv[i] = d; besti[i] = vb + 2; }
                d = fmaf(-2.0f, p1.y, Ci[i] + e3);
                if (d < bestv[i]) { bestv[i] = d; besti[i] = vb + 3; }
            }
        }
    }

    // cross-tx reduction: the 16 tx threads of one ty live in one half-warp
    #pragma unroll
    for (int i = 0; i < 8; i++) {
        float v = bestv[i];
        int   idx = besti[i];
        #pragma unroll
        for (int off = 8; off > 0; off >>= 1) {
            float ov = __shfl_xor_sync(0xffffffffu, v, off);
            int   oi = __shfl_xor_sync(0xffffffffu, idx, off);
            if (ov < v || (ov == v && oi < idx)) { v = ov; idx = oi; }
        }
        if (tx == 0) {
            int n = m0 + row0 + i;
            g_tok[n] = idx;
            out_tok[n] = (float)idx;
        }
    }
}

// ============================================================
// Kernel 3: z_q = emb[tok] @ post_W + post_b
// ============================================================
#define BM 64
#define BK 32

__global__ __launch_bounds__(256) void post_kernel(
    const float* __restrict__ emb, const float* __restrict__ W,
    const float* __restrict__ b, float* __restrict__ out)
{
    __shared__ float As[BK][BM + 4];
    __shared__ float Bs[BK][64 + 4];
    __shared__ int   toks[BM];

    int m0  = blockIdx.x * BM;
    int tid = threadIdx.x;
    int tx  = tid & 15;
    int ty  = tid >> 4;

    if (tid < BM) toks[tid] = g_tok[m0 + tid];
    __syncthreads();

    float acc[4][4];
    #pragma unroll
    for (int i = 0; i < 4; i++)
        #pragma unroll
        for (int j = 0; j < 4; j++) acc[i][j] = 0.f;

    for (int k0 = 0; k0 < E_DIM; k0 += BK) {
        #pragma unroll
        for (int i = 0; i < 8; i++) {
            int idx = tid + 256 * i;
            int m = idx >> 5, kk = idx & 31;
            As[kk][m] = emb[(size_t)toks[m] * E_DIM + k0 + kk];
        }
        #pragma unroll
        for (int i = 0; i < 8; i++) {
            int idx = tid + 256 * i;
            int kk = idx >> 6, j = idx & 63;
            Bs[kk][j] = W[(size_t)(k0 + kk) * 64 + j];
        }
        __syncthreads();
        #pragma unroll
        for (int kk = 0; kk < BK; kk++) {
            float a[4], bb[4];
            *(float4*)a  = *(const float4*)&As[kk][ty * 4];
            *(float4*)bb = *(const float4*)&Bs[kk][tx * 4];
            #pragma unroll
            for (int i = 0; i < 4; i++)
                #pragma unroll
                for (int j = 0; j < 4; j++)
                    acc[i][j] = fmaf(a[i], bb[j], acc[i][j]);
        }
        __syncthreads();
    }

    float bb0 = b[tx * 4 + 0], bb1 = b[tx * 4 + 1],
          bb2 = b[tx * 4 + 2], bb3 = b[tx * 4 + 3];
    #pragma unroll
    for (int i = 0; i < 4; i++) {
        int n = m0 + ty * 4 + i;
        float4 r;
        r.x = acc[i][0] + bb0;
        r.y = acc[i][1] + bb1;
        r.z = acc[i][2] + bb2;
        r.w = acc[i][3] + bb3;
        *(float4*)&out[(size_t)n * 64 + tx * 4] = r;
    }
}

// ============================================================
extern "C" void kernel_launch(void* const* d_in, const int* in_sizes, int n_in,
                              void* d_out, int out_size)
{
    const float* z      = (const float*)d_in[0];   // [N, 64]
    const float* emb_W  = (const float*)d_in[1];   // [2048, 512]
    const float* pre_W  = (const float*)d_in[2];   // [64, 512]
    const float* pre_b  = (const float*)d_in[3];   // [512]
    const float* post_W = (const float*)d_in[4];   // [512, 64]
    const float* post_b = (const float*)d_in[5];   // [64]

    float* out = (float*)d_out;
    float* out_tok = out;                 // [N] tokens (as float)
    float* out_zq  = out + N_TOK;         // [N, 64]

    e2_kernel  <<<V_SIZE, 128>>>(emb_W);
    pre_kernel <<<N_TOK, 128>>>(z, pre_W, pre_b);
    dist_kernel<<<N_TOK / DBM, 256>>>(emb_W, out_tok);
    post_kernel<<<N_TOK / BM, 256>>>(emb_W, post_W, post_b, out_zq);
}

// round 3
// speedup vs baseline: 2.2643x; 1.1786x over previous
#include <cuda_runtime.h>
#include <cstdint>

#define N_TOK   65536
#define K_IN    64
#define E_DIM   512
#define V_SIZE  2048

typedef unsigned long long ull;

// ---- scratch (device globals: no runtime allocation allowed) ----
__device__ float g_zp[(size_t)N_TOK * E_DIM];   // pre-conv output  [N, 512]
__device__ float g_C [N_TOK];                   // |zp|^2 per row
__device__ float g_e2[V_SIZE];                  // |emb|^2 per code
__device__ int   g_tok[N_TOK];                  // argmin tokens
__device__ float g_P [(size_t)V_SIZE * 64];     // emb @ post_W + post_b

// ---- packed fp32x2 helpers (each lane is exact IEEE fp32 FMA) ----
__device__ __forceinline__ ull fma2(ull a, ull b, ull c) {
    ull d;
    asm("fma.rn.f32x2 %0, %1, %2, %3;" : "=l"(d) : "l"(a), "l"(b), "l"(c));
    return d;
}
__device__ __forceinline__ ull dup2(float x) {
    ull d;
    asm("mov.b64 %0, {%1, %1};" : "=l"(d) : "f"(x));
    return d;
}
__device__ __forceinline__ ull pack2(float x, float y) {
    ull d;
    asm("mov.b64 %0, {%1, %2};" : "=l"(d) : "f"(x), "f"(y));
    return d;
}
__device__ __forceinline__ float2 unpack2(ull v) {
    float2 r;
    asm("mov.b64 {%0, %1}, %2;" : "=f"(r.x), "=f"(r.y) : "l"(v));
    return r;
}

// ============================================================
// Kernel 0: e2[v] = sum_k emb[v,k]^2
// ============================================================
__global__ void e2_kernel(const float* __restrict__ emb) {
    int v = blockIdx.x;
    const float* row = emb + (size_t)v * E_DIM;
    float s = 0.f;
    for (int k = threadIdx.x; k < E_DIM; k += 128) {
        float x = row[k];
        s = fmaf(x, x, s);
    }
    for (int off = 16; off > 0; off >>= 1)
        s += __shfl_down_sync(0xffffffffu, s, off);
    __shared__ float ws[4];
    int lane = threadIdx.x & 31, warp = threadIdx.x >> 5;
    if (lane == 0) ws[warp] = s;
    __syncthreads();
    if (threadIdx.x == 0)
        g_e2[v] = ws[0] + ws[1] + ws[2] + ws[3];
}

// ============================================================
// Kernel 1: zp = z @ pre_W + pre_b, and C = |zp|^2
// ============================================================
__global__ __launch_bounds__(128) void pre_kernel(
    const float* __restrict__ z, const float* __restrict__ W,
    const float* __restrict__ b)
{
    int n = blockIdx.x;
    __shared__ float zs[K_IN];
    if (threadIdx.x < K_IN) zs[threadIdx.x] = z[(size_t)n * K_IN + threadIdx.x];
    __syncthreads();

    int j0 = threadIdx.x;
    float acc[4];
    #pragma unroll
    for (int i = 0; i < 4; i++) acc[i] = b[j0 + 128 * i];

    #pragma unroll 8
    for (int k = 0; k < K_IN; k++) {
        float zk = zs[k];
        const float* Wr = W + (size_t)k * E_DIM + j0;
        #pragma unroll
        for (int i = 0; i < 4; i++)
            acc[i] = fmaf(zk, Wr[128 * i], acc[i]);
    }

    float* zpr = g_zp + (size_t)n * E_DIM + j0;
    float s = 0.f;
    #pragma unroll
    for (int i = 0; i < 4; i++) {
        zpr[128 * i] = acc[i];
        s = fmaf(acc[i], acc[i], s);
    }
    for (int off = 16; off > 0; off >>= 1)
        s += __shfl_down_sync(0xffffffffu, s, off);
    __shared__ float ws[4];
    int lane = threadIdx.x & 31, warp = threadIdx.x >> 5;
    if (lane == 0) ws[warp] = s;
    __syncthreads();
    if (threadIdx.x == 0)
        g_C[n] = ws[0] + ws[1] + ws[2] + ws[3];
}

// ============================================================
// Kernel 2: fused distance GEMM + argmin, packed FFMA2,
// software-pipelined with register prefetch.
// block tile 128 rows x 256 codes x K16; 256 threads;
// per thread 8 rows x 16 codes. Per-output FMA chain is the
// sequential k=0..511 order -> bitwise identical tokens.
// ============================================================
#define DBM 128
#define DBV 256
#define DBK 16
#define NKT (E_DIM / DBK)            // 32 k-tiles
#define NVT (V_SIZE / DBV)           // 8 v-tiles
#define NT  (NKT * NVT)              // 256 total tiles

__global__ __launch_bounds__(256, 1) void dist_kernel(
    const float* __restrict__ emb, float* __restrict__ out_tok)
{
    __shared__ float As[DBK][DBM + 4];
    __shared__ float Bs[DBK][DBV + 4];

    int m0  = blockIdx.x * DBM;
    int tid = threadIdx.x;
    int tx  = tid & 15;    // code direction
    int ty  = tid >> 4;    // row direction
    int row0 = ty * 8;

    // per-thread constant load/store geometry
    int mA  = tid >> 2;            // 0..63  (A row within first half)
    int kq4 = (tid & 3) * 4;       // k offset within tile
    const float* aBase = g_zp + (size_t)(m0 + mA) * E_DIM + kq4;
    float* sA0 = &As[kq4][mA];
    float* sA1 = &As[kq4][mA + 64];

    float Ci[8];
    #pragma unroll
    for (int i = 0; i < 8; i++) Ci[i] = g_C[m0 + row0 + i];

    float bestv[8];
    int   besti[8];
    #pragma unroll
    for (int i = 0; i < 8; i++) { bestv[i] = 3.4e38f; besti[i] = 0; }

    ull acc[8][8];

    // prefetch tile 0
    float4 pA[2], pB[4];
    {
        pA[0] = *(const float4*)(aBase);
        pA[1] = *(const float4*)(aBase + (size_t)64 * E_DIM);
        const float* bBase = emb + (size_t)mA * E_DIM + kq4;
        #pragma unroll
        for (int l = 0; l < 4; l++)
            pB[l] = *(const float4*)(bBase + (size_t)(64 * l) * E_DIM);
    }

    for (int t = 0; t < NT; t++) {
        // ---- store prefetched tile to smem (transpose) ----
        sA0[0*(DBM+4)] = pA[0].x; sA0[1*(DBM+4)] = pA[0].y;
        sA0[2*(DBM+4)] = pA[0].z; sA0[3*(DBM+4)] = pA[0].w;
        sA1[0*(DBM+4)] = pA[1].x; sA1[1*(DBM+4)] = pA[1].y;
        sA1[2*(DBM+4)] = pA[1].z; sA1[3*(DBM+4)] = pA[1].w;
        #pragma unroll
        for (int l = 0; l < 4; l++) {
            float* sB = &Bs[kq4][mA + 64 * l];
            sB[0*(DBV+4)] = pB[l].x; sB[1*(DBV+4)] = pB[l].y;
            sB[2*(DBV+4)] = pB[l].z; sB[3*(DBV+4)] = pB[l].w;
        }

        // ---- issue prefetch for tile t+1 (latency hidden by compute) ----
        {
            int tn = (t + 1 < NT) ? t + 1 : t;
            int k1 = (tn & (NKT - 1)) * DBK;
            int v1 = (tn >> 5) * DBV;
            pA[0] = *(const float4*)(aBase + k1);
            pA[1] = *(const float4*)(aBase + (size_t)64 * E_DIM + k1);
            const float* bBase = emb + (size_t)(v1 + mA) * E_DIM + kq4 + k1;
            #pragma unroll
            for (int l = 0; l < 4; l++)
                pB[l] = *(const float4*)(bBase + (size_t)(64 * l) * E_DIM);
        }

        if ((t & (NKT - 1)) == 0) {
            #pragma unroll
            for (int i = 0; i < 8; i++)
                #pragma unroll
                for (int j = 0; j < 8; j++) acc[i][j] = 0ull;
        }

        __syncthreads();

        // ---- compute 16 kk steps ----
        #pragma unroll
        for (int kk = 0; kk < DBK; kk++) {
            float4 a01 = *(const float4*)&As[kk][row0];
            float4 a23 = *(const float4*)&As[kk][row0 + 4];
            ull ad[8];
            ad[0] = dup2(a01.x); ad[1] = dup2(a01.y);
            ad[2] = dup2(a01.z); ad[3] = dup2(a01.w);
            ad[4] = dup2(a23.x); ad[5] = dup2(a23.y);
            ad[6] = dup2(a23.z); ad[7] = dup2(a23.w);
            #pragma unroll
            for (int g = 0; g < 4; g++) {
                float4 b = *(const float4*)&Bs[kk][(g * 16 + tx) * 4];
                ull b0 = pack2(b.x, b.y);
                ull b1 = pack2(b.z, b.w);
                #pragma unroll
                for (int i = 0; i < 8; i++) {
                    acc[i][g * 2 + 0] = fma2(ad[i], b0, acc[i][g * 2 + 0]);
                    acc[i][g * 2 + 1] = fma2(ad[i], b1, acc[i][g * 2 + 1]);
                }
            }
        }

        __syncthreads();

        // ---- end of a v0 group: fold argmin ----
        if ((t & (NKT - 1)) == NKT - 1) {
            int v0 = (t >> 5) * DBV;
            #pragma unroll
            for (int g = 0; g < 4; g++) {
                int vb = v0 + (g * 16 + tx) * 4;
                float e0 = g_e2[vb + 0];
                float e1 = g_e2[vb + 1];
                float e2v = g_e2[vb + 2];
                float e3 = g_e2[vb + 3];
                #pragma unroll
                for (int i = 0; i < 8; i++) {
                    float2 p0 = unpack2(acc[i][g * 2 + 0]);
                    float2 p1 = unpack2(acc[i][g * 2 + 1]);
                    float d;
                    d = fmaf(-2.0f, p0.x, Ci[i] + e0);
                    if (d < bestv[i]) { bestv[i] = d; besti[i] = vb + 0; }
                    d = fmaf(-2.0f, p0.y, Ci[i] + e1);
                    if (d < bestv[i]) { bestv[i] = d; besti[i] = vb + 1; }
                    d = fmaf(-2.0f, p1.x, Ci[i] + e2v);
                    if (d < bestv[i]) { bestv[i] = d; besti[i] = vb + 2; }
                    d = fmaf(-2.0f, p1.y, Ci[i] + e3);
                    if (d < bestv[i]) { bestv[i] = d; besti[i] = vb + 3; }
                }
            }
        }
    }

    // cross-tx reduction (16 tx threads of a ty are in one half-warp)
    #pragma unroll
    for (int i = 0; i < 8; i++) {
        float v = bestv[i];
        int   idx = besti[i];
        #pragma unroll
        for (int off = 8; off > 0; off >>= 1) {
            float ov = __shfl_xor_sync(0xffffffffu, v, off);
            int   oi = __shfl_xor_sync(0xffffffffu, idx, off);
            if (ov < v || (ov == v && oi < idx)) { v = ov; idx = oi; }
        }
        if (tx == 0) {
            int n = m0 + row0 + i;
            g_tok[n] = idx;
            out_tok[n] = (float)idx;
        }
    }
}

// ============================================================
// Kernel 3: P = emb @ post_W + post_b   [2048, 64]
// 64 rows x 64 cols per block, K32 tiles (same chain as before)
// ============================================================
#define BM 64
#define BK 32

__global__ __launch_bounds__(256) void pmat_kernel(
    const float* __restrict__ emb, const float* __restrict__ W,
    const float* __restrict__ b)
{
    __shared__ float As[BK][BM + 4];
    __shared__ float Bs[BK][64 + 4];

    int m0  = blockIdx.x * BM;
    int tid = threadIdx.x;
    int tx  = tid & 15;
    int ty  = tid >> 4;

    float acc[4][4];
    #pragma unroll
    for (int i = 0; i < 4; i++)
        #pragma unroll
        for (int j = 0; j < 4; j++) acc[i][j] = 0.f;

    for (int k0 = 0; k0 < E_DIM; k0 += BK) {
        #pragma unroll
        for (int i = 0; i < 8; i++) {
            int idx = tid + 256 * i;
            int m = idx >> 5, kk = idx & 31;
            As[kk][m] = emb[(size_t)(m0 + m) * E_DIM + k0 + kk];
        }
        #pragma unroll
        for (int i = 0; i < 8; i++) {
            int idx = tid + 256 * i;
            int kk = idx >> 6, j = idx & 63;
            Bs[kk][j] = W[(size_t)(k0 + kk) * 64 + j];
        }
        __syncthreads();
        #pragma unroll
        for (int kk = 0; kk < BK; kk++) {
            float a[4], bb[4];
            *(float4*)a  = *(const float4*)&As[kk][ty * 4];
            *(float4*)bb = *(const float4*)&Bs[kk][tx * 4];
            #pragma unroll
            for (int i = 0; i < 4; i++)
                #pragma unroll
                for (int j = 0; j < 4; j++)
                    acc[i][j] = fmaf(a[i], bb[j], acc[i][j]);
        }
        __syncthreads();
    }

    float bb0 = b[tx * 4 + 0], bb1 = b[tx * 4 + 1],
          bb2 = b[tx * 4 + 2], bb3 = b[tx * 4 + 3];
    #pragma unroll
    for (int i = 0; i < 4; i++) {
        int n = m0 + ty * 4 + i;
        float4 r;
        r.x = acc[i][0] + bb0;
        r.y = acc[i][1] + bb1;
        r.z = acc[i][2] + bb2;
        r.w = acc[i][3] + bb3;
        *(float4*)&g_P[(size_t)n * 64 + tx * 4] = r;
    }
}

// ============================================================
// Kernel 4: z_q[n] = P[tok[n]]  (pure gather, memory bound)
// one float4 per thread
// ============================================================
__global__ __launch_bounds__(256) void gather_kernel(float* __restrict__ out)
{
    int idx = blockIdx.x * 256 + threadIdx.x;   // 0 .. N_TOK*16
    int n = idx >> 4;
    int c = idx & 15;
    int tok = g_tok[n];
    float4 v = *(const float4*)&g_P[(size_t)tok * 64 + c * 4];
    *(float4*)&out[(size_t)n * 64 + c * 4] = v;
}

// ============================================================
extern "C" void kernel_launch(void* const* d_in, const int* in_sizes, int n_in,
                              void* d_out, int out_size)
{
    const float* z      = (const float*)d_in[0];   // [N, 64]
    const float* emb_W  = (const float*)d_in[1];   // [2048, 512]
    const float* pre_W  = (const float*)d_in[2];   // [64, 512]
    const float* pre_b  = (const float*)d_in[3];   // [512]
    const float* post_W = (const float*)d_in[4];   // [512, 64]
    const float* post_b = (const float*)d_in[5];   // [64]

    float* out = (float*)d_out;
    float* out_tok = out;                 // [N] tokens (as float)
    float* out_zq  = out + N_TOK;         // [N, 64]

    e2_kernel   <<<V_SIZE, 128>>>(emb_W);
    pre_kernel  <<<N_TOK, 128>>>(z, pre_W, pre_b);
    pmat_kernel <<<V_SIZE / BM, 256>>>(emb_W, post_W, post_b);
    dist_kernel <<<N_TOK / DBM, 256>>>(emb_W, out_tok);
    gather_kernel<<<(N_TOK * 16) / 256, 256>>>(out_zq);
}